// round 3
// baseline (speedup 1.0000x reference)
#include <cuda_runtime.h>
#include <cuda_bf16.h>
#include <cstddef>

// LIF activation over time axis.
// x: [B=64, T=500, C=1024] fp32; w_input, w_leak: device scalars.
// out: spikes [B, T, C] fp32 (0.0/1.0).
//
// R2 -> R3: the compiler was sinking the front-batched loads to their uses
// (regs=32 proved it; MLP_eff ~6, DRAM stuck at 49%). Force 20 genuinely
// outstanding LDGs per warp with asm volatile loads, which ptxas cannot
// reorder or sink. 2048 warps * 20 * 128B = 5.2MB in flight vs ~2.6MB
// needed to saturate HBM.

#define LIF_B 64
#define LIF_T 500
#define LIF_C 1024
#define LIF_UNROLL 20
#define LIF_BLOCK 64

__global__ __launch_bounds__(LIF_BLOCK) void lif_kernel(
    const float* __restrict__ x,
    const float* __restrict__ w_input_p,
    const float* __restrict__ w_leak_p,
    float* __restrict__ out)
{
    const int tid = blockIdx.x * blockDim.x + threadIdx.x;  // 0 .. B*C-1
    const float wi   = *w_input_p;
    const float keep = 1.0f - *w_leak_p;

    const int b = tid >> 10;        // / C
    const int c = tid & (LIF_C - 1);

    const size_t base = (size_t)b * LIF_T * LIF_C + c;
    const float* xp = x + base;
    float* op = out + base;

    float Vm = 0.0f;

    #pragma unroll 1
    for (int t0 = 0; t0 < LIF_T; t0 += LIF_UNROLL) {
        // 20 forced-in-flight loads. asm volatile pins both the issue order
        // and the liveness of all 20 destination registers.
        float xv[LIF_UNROLL];
        #pragma unroll
        for (int i = 0; i < LIF_UNROLL; i++) {
            const float* p = xp + (size_t)(t0 + i) * LIF_C;
            asm volatile("ld.global.nc.f32 %0, [%1];" : "=f"(xv[i]) : "l"(p));
        }

        // Sequential recurrence; store each spike as soon as it's known.
        #pragma unroll
        for (int i = 0; i < LIF_UNROLL; i++) {
            const float forget = ((1.0f - Vm) > 0.0f) ? 1.0f : 0.0f;
            const float v = wi * xv[i] + keep * Vm * forget;
            Vm = fmaxf(v, 0.0f);
            op[(size_t)(t0 + i) * LIF_C] = ((Vm - 1.0f) > 0.0f) ? 1.0f : 0.0f;
        }
    }
}

extern "C" void kernel_launch(void* const* d_in, const int* in_sizes, int n_in,
                              void* d_out, int out_size) {
    const float* x        = (const float*)d_in[0];
    const float* w_input  = (const float*)d_in[1];
    const float* w_leak   = (const float*)d_in[2];
    float* out            = (float*)d_out;

    const int lanes = LIF_B * LIF_C;  // 65536
    lif_kernel<<<lanes / LIF_BLOCK, LIF_BLOCK>>>(x, w_input, w_leak, out);
}